// round 1
// baseline (speedup 1.0000x reference)
#include <cuda_runtime.h>
#include <math.h>

#define SQ 2048
#define DIM 2048
#define NH 16
#define HD 128
#define HID 5632

// ---------------- scratch (device globals; no allocation allowed) ----------------
__device__ float g_xn[SQ * DIM];
__device__ float g_q [SQ * DIM];
__device__ float g_k [SQ * DIM];
__device__ float g_v [SQ * DIM];
__device__ float g_ao[SQ * DIM];
__device__ float g_h [SQ * DIM];
__device__ float g_hn[SQ * DIM];
__device__ float g_f1[SQ * HID];
__device__ float g_f3[SQ * HID];

// ---------------- rmsnorm ----------------
__global__ void rmsnorm_k(const float* __restrict__ x, const float* __restrict__ g,
                          float* __restrict__ o) {
    int row = blockIdx.x;
    const float* xr = x + (size_t)row * DIM;
    float ss = 0.f;
    for (int i = threadIdx.x; i < DIM; i += blockDim.x) { float v = xr[i]; ss += v * v; }
    __shared__ float red[32];
    int lane = threadIdx.x & 31, w = threadIdx.x >> 5;
    #pragma unroll
    for (int off = 16; off; off >>= 1) ss += __shfl_xor_sync(0xffffffffu, ss, off);
    if (lane == 0) red[w] = ss;
    __syncthreads();
    if (w == 0) {
        float v = (lane < (int)(blockDim.x >> 5)) ? red[lane] : 0.f;
        #pragma unroll
        for (int off = 16; off; off >>= 1) v += __shfl_xor_sync(0xffffffffu, v, off);
        if (lane == 0) red[0] = v;
    }
    __syncthreads();
    float inv = rsqrtf(red[0] / (float)DIM + 1e-6f);
    float* orow = o + (size_t)row * DIM;
    for (int i = threadIdx.x; i < DIM; i += blockDim.x) orow[i] = g[i] * xr[i] * inv;
}

// ---------------- SGEMM: C[M,N] = A[M,K] @ B[K,N] (+ optional residual R) ----------------
template <int RES>
__global__ __launch_bounds__(256, 2) void sgemm_k(
    const float* __restrict__ A, const float* __restrict__ B,
    const float* __restrict__ R, float* __restrict__ C,
    int M, int N, int K) {
    const int BM = 128, BN = 128, BK = 8, TM = 8, TN = 8;
    __shared__ float As[BK * BM];
    __shared__ float Bs[BK * BN];
    int tid = threadIdx.x;
    int bx = blockIdx.x, by = blockIdx.y;
    const float* Ab = A + (size_t)by * BM * K;
    const float* Bb = B + (size_t)bx * BN;

    int aRow = tid >> 1;          // 0..127
    int aCol = (tid & 1) * 4;     // 0 or 4
    int bRow = tid >> 5;          // 0..7
    int bCol = (tid & 31) * 4;    // 0..124
    int tRow = (tid >> 4) * TM;
    int tCol = (tid & 15) * TN;

    float acc[TM][TN];
    #pragma unroll
    for (int i = 0; i < TM; i++)
        #pragma unroll
        for (int j = 0; j < TN; j++) acc[i][j] = 0.f;

    for (int k0 = 0; k0 < K; k0 += BK) {
        float4 a4 = *(const float4*)(Ab + (size_t)aRow * K + k0 + aCol);
        As[(aCol + 0) * BM + aRow] = a4.x;
        As[(aCol + 1) * BM + aRow] = a4.y;
        As[(aCol + 2) * BM + aRow] = a4.z;
        As[(aCol + 3) * BM + aRow] = a4.w;
        *(float4*)(&Bs[bRow * BN + bCol]) =
            *(const float4*)(Bb + (size_t)(k0 + bRow) * N + bCol);
        __syncthreads();
        #pragma unroll
        for (int kk = 0; kk < BK; kk++) {
            float4 m0 = *(const float4*)(&As[kk * BM + tRow]);
            float4 m1 = *(const float4*)(&As[kk * BM + tRow + 4]);
            float4 n0 = *(const float4*)(&Bs[kk * BN + tCol]);
            float4 n1 = *(const float4*)(&Bs[kk * BN + tCol + 4]);
            float rm[8] = {m0.x, m0.y, m0.z, m0.w, m1.x, m1.y, m1.z, m1.w};
            float rn[8] = {n0.x, n0.y, n0.z, n0.w, n1.x, n1.y, n1.z, n1.w};
            #pragma unroll
            for (int i = 0; i < TM; i++)
                #pragma unroll
                for (int j = 0; j < TN; j++) acc[i][j] += rm[i] * rn[j];
        }
        __syncthreads();
    }

    #pragma unroll
    for (int i = 0; i < TM; i++) {
        size_t off = (size_t)(by * BM + tRow + i) * N + bx * BN + tCol;
        #pragma unroll
        for (int j0 = 0; j0 < TN; j0 += 4) {
            float4 cv = make_float4(acc[i][j0], acc[i][j0 + 1], acc[i][j0 + 2], acc[i][j0 + 3]);
            if (RES) {
                float4 rv = *(const float4*)(R + off + j0);
                cv.x += rv.x; cv.y += rv.y; cv.z += rv.z; cv.w += rv.w;
            }
            *(float4*)(C + off + j0) = cv;
        }
    }
}

// ---------------- RoPE on q and k in-place ----------------
__global__ void rope_k(float* __restrict__ q, float* __restrict__ k,
                       const float* __restrict__ fc, const float* __restrict__ fs) {
    int i = blockIdx.x * blockDim.x + threadIdx.x;  // SQ*NH*64 threads
    if (i >= SQ * NH * (HD / 2)) return;
    int p = i & 63;
    int h = (i >> 6) & (NH - 1);
    int s = i >> 10;
    float c = fc[s * 64 + p], sn = fs[s * 64 + p];
    size_t base = (size_t)s * DIM + h * HD + 2 * p;
    float2 qv = *(float2*)(q + base);
    float2 kv = *(float2*)(k + base);
    float2 qo = make_float2(qv.x * c - qv.y * sn, qv.x * sn + qv.y * c);
    float2 ko = make_float2(kv.x * c - kv.y * sn, kv.x * sn + kv.y * c);
    *(float2*)(q + base) = qo;
    *(float2*)(k + base) = ko;
}

// ---------------- causal flash attention ----------------
#define BQ 32
#define BKK 32
#define KPAD 132   // 128 + 4: float4-aligned, bank-spread
#define SCPAD 33

#define ATTN_SMEM ((BQ * KPAD + 2 * BKK * KPAD + BQ * SCPAD) * 4)

__global__ __launch_bounds__(256) void attn_k(
    const float* __restrict__ q, const float* __restrict__ k,
    const float* __restrict__ v, float* __restrict__ o) {
    extern __shared__ float sm[];
    float* Qs = sm;                      // BQ  * KPAD
    float* Ks = Qs + BQ * KPAD;          // BKK * KPAD
    float* Vs = Ks + BKK * KPAD;         // BKK * KPAD
    float* sc = Vs + BKK * KPAD;         // BQ  * SCPAD

    int tid = threadIdx.x;               // 256
    int h = blockIdx.y;
    int q0 = blockIdx.x * BQ;

    // load Q tile (float4): 32 rows x 128 cols = 1024 float4s
    #pragma unroll
    for (int r = 0; r < 4; r++) {
        int idx = tid + 256 * r;
        int row = idx >> 5;
        int c4 = (idx & 31) << 2;
        *(float4*)(&Qs[row * KPAD + c4]) =
            *(const float4*)(q + (size_t)(q0 + row) * DIM + h * HD + c4);
    }

    int qr = tid >> 3;       // query row within tile (0..31), 8 threads per row
    int kl = tid & 7;        // lane within row group
    int qg = q0 + qr;

    float m = -INFINITY, l = 0.f;
    float4 acc4[4];
    #pragma unroll
    for (int ii = 0; ii < 4; ii++) acc4[ii] = make_float4(0.f, 0.f, 0.f, 0.f);

    const float scale = 0.08838834764831845f;  // 1/sqrt(128)
    int ntiles = blockIdx.x + 1;

    for (int t = 0; t < ntiles; t++) {
        int j0 = t * BKK;
        __syncthreads();  // protect Ks/Vs/sc from previous iteration's readers
        #pragma unroll
        for (int r = 0; r < 4; r++) {
            int idx = tid + 256 * r;
            int row = idx >> 5;
            int c4 = (idx & 31) << 2;
            *(float4*)(&Ks[row * KPAD + c4]) =
                *(const float4*)(k + (size_t)(j0 + row) * DIM + h * HD + c4);
            *(float4*)(&Vs[row * KPAD + c4]) =
                *(const float4*)(v + (size_t)(j0 + row) * DIM + h * HD + c4);
        }
        __syncthreads();

        // scores: 4 keys per thread, j = kl + 8*i
        float s0 = 0.f, s1 = 0.f, s2 = 0.f, s3 = 0.f;
        #pragma unroll 8
        for (int d = 0; d < HD; d += 4) {
            float4 q4 = *(const float4*)(&Qs[qr * KPAD + d]);
            float4 k0v = *(const float4*)(&Ks[(kl + 0)  * KPAD + d]);
            float4 k1v = *(const float4*)(&Ks[(kl + 8)  * KPAD + d]);
            float4 k2v = *(const float4*)(&Ks[(kl + 16) * KPAD + d]);
            float4 k3v = *(const float4*)(&Ks[(kl + 24) * KPAD + d]);
            s0 += q4.x * k0v.x + q4.y * k0v.y + q4.z * k0v.z + q4.w * k0v.w;
            s1 += q4.x * k1v.x + q4.y * k1v.y + q4.z * k1v.z + q4.w * k1v.w;
            s2 += q4.x * k2v.x + q4.y * k2v.y + q4.z * k2v.z + q4.w * k2v.w;
            s3 += q4.x * k3v.x + q4.y * k3v.y + q4.z * k3v.z + q4.w * k3v.w;
        }
        float sv[4] = {s0, s1, s2, s3};
        #pragma unroll
        for (int i = 0; i < 4; i++) {
            int j = kl + 8 * i;
            float s = sv[i] * scale;
            if (j0 + j > qg) s = -INFINITY;
            sc[qr * SCPAD + j] = s;
        }
        __syncthreads();

        // row max (redundant per row group, deterministic)
        float tmax = -INFINITY;
        #pragma unroll 8
        for (int j = 0; j < BKK; j++) tmax = fmaxf(tmax, sc[qr * SCPAD + j]);
        float nm = fmaxf(m, tmax);
        float alpha = __expf(m - nm);
        __syncthreads();  // all score reads done before overwrite

        #pragma unroll
        for (int i = 0; i < 4; i++) {
            int j = kl + 8 * i;
            float s = sc[qr * SCPAD + j];
            sc[qr * SCPAD + j] = (s == -INFINITY) ? 0.f : __expf(s - nm);
        }
        __syncthreads();

        float ps = 0.f;
        #pragma unroll 8
        for (int j = 0; j < BKK; j++) ps += sc[qr * SCPAD + j];
        l = l * alpha + ps;
        m = nm;

        #pragma unroll
        for (int ii = 0; ii < 4; ii++) {
            acc4[ii].x *= alpha; acc4[ii].y *= alpha;
            acc4[ii].z *= alpha; acc4[ii].w *= alpha;
        }
        // thread owns dims d = kl*4 + 32*ii + c (float4 chunks, bank-spread)
        #pragma unroll 4
        for (int j = 0; j < BKK; j++) {
            float p = sc[qr * SCPAD + j];
            #pragma unroll
            for (int ii = 0; ii < 4; ii++) {
                float4 vv = *(const float4*)(&Vs[j * KPAD + kl * 4 + 32 * ii]);
                acc4[ii].x += p * vv.x; acc4[ii].y += p * vv.y;
                acc4[ii].z += p * vv.z; acc4[ii].w += p * vv.w;
            }
        }
    }

    float invl = 1.f / l;
    #pragma unroll
    for (int ii = 0; ii < 4; ii++) {
        float4 r = make_float4(acc4[ii].x * invl, acc4[ii].y * invl,
                               acc4[ii].z * invl, acc4[ii].w * invl);
        *(float4*)(&o[(size_t)qg * DIM + h * HD + kl * 4 + 32 * ii]) = r;
    }
}

// ---------------- silu(a) * b -> a ----------------
__global__ void silu_mul_k(float* __restrict__ a, const float* __restrict__ b, int n4) {
    int i = blockIdx.x * blockDim.x + threadIdx.x;
    if (i >= n4) return;
    float4 av = *(float4*)(&a[i * 4]);
    float4 bv = *(const float4*)(&b[i * 4]);
    av.x = av.x / (1.f + __expf(-av.x)) * bv.x;
    av.y = av.y / (1.f + __expf(-av.y)) * bv.y;
    av.z = av.z / (1.f + __expf(-av.z)) * bv.z;
    av.w = av.w / (1.f + __expf(-av.w)) * bv.w;
    *(float4*)(&a[i * 4]) = av;
}

// ---------------- launcher ----------------
extern "C" void kernel_launch(void* const* d_in, const int* in_sizes, int n_in,
                              void* d_out, int out_size) {
    const float* x  = (const float*)d_in[0];
    const float* fc = (const float*)d_in[1];
    const float* fs = (const float*)d_in[2];
    // d_in[3] = mask (causal, implicit — unused)
    const float* wq = (const float*)d_in[4];
    const float* wk = (const float*)d_in[5];
    const float* wv = (const float*)d_in[6];
    const float* wo = (const float*)d_in[7];
    const float* w1 = (const float*)d_in[8];
    const float* w2 = (const float*)d_in[9];
    const float* w3 = (const float*)d_in[10];
    const float* ga = (const float*)d_in[11];
    const float* gf = (const float*)d_in[12];
    float* out = (float*)d_out;

    float *xn, *q, *k, *v, *ao, *h, *hn, *f1, *f3;
    cudaGetSymbolAddress((void**)&xn, g_xn);
    cudaGetSymbolAddress((void**)&q,  g_q);
    cudaGetSymbolAddress((void**)&k,  g_k);
    cudaGetSymbolAddress((void**)&v,  g_v);
    cudaGetSymbolAddress((void**)&ao, g_ao);
    cudaGetSymbolAddress((void**)&h,  g_h);
    cudaGetSymbolAddress((void**)&hn, g_hn);
    cudaGetSymbolAddress((void**)&f1, g_f1);
    cudaGetSymbolAddress((void**)&f3, g_f3);

    cudaFuncSetAttribute(attn_k, cudaFuncAttributeMaxDynamicSharedMemorySize, ATTN_SMEM);

    // 1. pre-attn rmsnorm
    rmsnorm_k<<<SQ, 256>>>(x, ga, xn);

    // 2. q,k,v projections
    dim3 gDD(DIM / 128, SQ / 128);
    sgemm_k<0><<<gDD, 256>>>(xn, wq, nullptr, q, SQ, DIM, DIM);
    sgemm_k<0><<<gDD, 256>>>(xn, wk, nullptr, k, SQ, DIM, DIM);
    sgemm_k<0><<<gDD, 256>>>(xn, wv, nullptr, v, SQ, DIM, DIM);

    // 3. rope
    rope_k<<<(SQ * NH * (HD / 2)) / 256, 256>>>(q, k, fc, fs);

    // 4. causal attention
    attn_k<<<dim3(SQ / BQ, NH), 256, ATTN_SMEM>>>(q, k, v, ao);

    // 5. output projection + residual
    sgemm_k<1><<<gDD, 256>>>(ao, wo, x, h, SQ, DIM, DIM);

    // 6. pre-ffn rmsnorm
    rmsnorm_k<<<SQ, 256>>>(h, gf, hn);

    // 7. ffn up projections
    dim3 gDH(HID / 128, SQ / 128);
    sgemm_k<0><<<gDH, 256>>>(hn, w1, nullptr, f1, SQ, HID, DIM);
    sgemm_k<0><<<gDH, 256>>>(hn, w3, nullptr, f3, SQ, HID, DIM);

    // 8. silu gate
    silu_mul_k<<<(SQ * HID / 4 + 255) / 256, 256>>>(f1, f3, SQ * HID / 4);

    // 9. down projection + residual -> output
    sgemm_k<1><<<gDD, 256>>>(f1, w2, h, out, SQ, DIM, HID);
}

// round 4
// speedup vs baseline: 1.7082x; 1.7082x over previous
#include <cuda_runtime.h>
#include <cuda_bf16.h>
#include <math.h>
#include <stdint.h>

#define SQ 2048
#define DIM 2048
#define NH 16
#define HD 128
#define HID 5632

// K-expanded split-bf16: K2 = 3*K
#define K2_DIM (3 * DIM)   // 6144
#define K2_HID (3 * HID)   // 16896

__device__ __forceinline__ uint32_t smem_u32(const void* p) {
    uint32_t a;
    asm("{ .reg .u64 t; cvta.to.shared.u64 t, %1; cvt.u32.u64 %0, t; }" : "=r"(a) : "l"(p));
    return a;
}
__device__ __forceinline__ void cp16(uint32_t s, const void* g) {
    asm volatile("cp.async.cg.shared.global [%0], [%1], 16;" :: "r"(s), "l"(g));
}

// ---------------- scratch ----------------
__device__ float g_q [SQ * DIM];
__device__ float g_k [SQ * DIM];
__device__ float g_v [SQ * DIM];
__device__ float g_h [SQ * DIM];
__device__ float g_f1[SQ * HID];
__device__ float g_f3[SQ * HID];

__device__ __nv_bfloat16 g_xnb[SQ * K2_DIM];
__device__ __nv_bfloat16 g_aob[SQ * K2_DIM];
__device__ __nv_bfloat16 g_hnb[SQ * K2_DIM];
__device__ __nv_bfloat16 g_fgb[SQ * K2_HID];
__device__ __nv_bfloat16 g_wqt[DIM * K2_DIM];
__device__ __nv_bfloat16 g_wkt[DIM * K2_DIM];
__device__ __nv_bfloat16 g_wvt[DIM * K2_DIM];
__device__ __nv_bfloat16 g_wot[DIM * K2_DIM];
__device__ __nv_bfloat16 g_w1t[HID * K2_DIM];
__device__ __nv_bfloat16 g_w3t[HID * K2_DIM];
__device__ __nv_bfloat16 g_w2t[DIM * K2_HID];

__device__ __forceinline__ void split3_A(float x, __nv_bfloat16* p) {
    __nv_bfloat16 hi = __float2bfloat16(x);
    __nv_bfloat16 lo = __float2bfloat16(x - __bfloat162float(hi));
    p[0] = hi; p[1] = lo; p[2] = hi;   // A side: {hi, lo, hi}
}
__device__ __forceinline__ void split3_B(float x, __nv_bfloat16* p) {
    __nv_bfloat16 hi = __float2bfloat16(x);
    __nv_bfloat16 lo = __float2bfloat16(x - __bfloat162float(hi));
    p[0] = hi; p[1] = hi; p[2] = lo;   // B side: {hi, hi, lo}
}

// ---------------- weight transpose + split: W[K,N] -> Wt[N, 3K] ----------------
__global__ void convert_w_t(const float* __restrict__ W, __nv_bfloat16* __restrict__ Wt,
                            int K, int N) {
    __shared__ float s[32][33];
    int k0 = blockIdx.x * 32, n0 = blockIdx.y * 32;
    int tx = threadIdx.x & 31, ty = threadIdx.x >> 5;  // 256 threads
    #pragma unroll
    for (int r = 0; r < 4; r++) {
        int k = ty + r * 8;
        s[k][tx] = W[(size_t)(k0 + k) * N + n0 + tx];
    }
    __syncthreads();
    int K3 = 3 * K;
    #pragma unroll
    for (int r = 0; r < 4; r++) {
        int n = ty + r * 8;
        split3_B(s[tx][n], Wt + (size_t)(n0 + n) * K3 + 3 * (k0 + tx));
    }
}

// ---------------- rmsnorm -> split-bf16 A operand ----------------
__global__ void rmsnorm_big_k(const float* __restrict__ x, const float* __restrict__ g,
                              __nv_bfloat16* __restrict__ o) {
    int row = blockIdx.x;
    const float* xr = x + (size_t)row * DIM;
    float ss = 0.f;
    for (int i = threadIdx.x; i < DIM; i += blockDim.x) { float v = xr[i]; ss += v * v; }
    __shared__ float red[32];
    int lane = threadIdx.x & 31, w = threadIdx.x >> 5;
    #pragma unroll
    for (int off = 16; off; off >>= 1) ss += __shfl_xor_sync(0xffffffffu, ss, off);
    if (lane == 0) red[w] = ss;
    __syncthreads();
    if (w == 0) {
        float v = (lane < (int)(blockDim.x >> 5)) ? red[lane] : 0.f;
        #pragma unroll
        for (int off = 16; off; off >>= 1) v += __shfl_xor_sync(0xffffffffu, v, off);
        if (lane == 0) red[0] = v;
    }
    __syncthreads();
    float inv = rsqrtf(red[0] / (float)DIM + 1e-6f);
    __nv_bfloat16* orow = o + (size_t)row * (3 * DIM);
    for (int i = threadIdx.x; i < DIM; i += blockDim.x)
        split3_A(g[i] * xr[i] * inv, orow + 3 * i);
}

// ---------------- silu(f1)*f3 -> split-bf16 A operand ----------------
__global__ void silu_big_k(const float* __restrict__ a, const float* __restrict__ b,
                           __nv_bfloat16* __restrict__ o, int n) {
    int i = blockIdx.x * blockDim.x + threadIdx.x;
    if (i >= n) return;
    float av = a[i];
    float v = av / (1.f + __expf(-av)) * b[i];
    split3_A(v, o + (size_t)3 * i);
}

// ---------------- HMMA bf16 GEMM: C[M,N] = A[M,K2] @ B[N,K2]^T (+R) ----------------
// CTA 128x128, 8 warps (2x4), warp 64x32, BK=32, 3-stage cp.async.
#define GBM 128
#define GBN 128
#define GBK 32
#define AROWB 80                  // 64B data + 16B pad per smem row
#define OPB (128 * AROWB)         // 10240 bytes per operand per stage
#define STGB (2 * OPB)            // 20480 per stage
#define GNST 3
#define HGEMM_SMEM (GNST * STGB)  // 61440

template <int RES>
__global__ __launch_bounds__(256, 2) void hgemm_k(
    const __nv_bfloat16* __restrict__ A, const __nv_bfloat16* __restrict__ B,
    const float* __restrict__ R, float* __restrict__ C,
    int M, int N, int K2) {
    extern __shared__ char sm[];
    uint32_t sb = smem_u32(sm);

    const int tid = threadIdx.x;
    const int wid = tid >> 5, lane = tid & 31;
    const int m0 = blockIdx.y * GBM, n0 = blockIdx.x * GBN;
    const int wm = (wid >> 2) * 64;       // warp m offset in tile
    const int wn = (wid & 3) * 32;        // warp n offset in tile

    // per-thread load coords (A and B identical pattern)
    const int ldrow = tid >> 2;           // 0..63 (x2 iterations -> 128 rows)
    const int ldc16 = tid & 3;            // 16B chunk within 64B row

    const __nv_bfloat16* Abase = A + (size_t)m0 * K2;
    const __nv_bfloat16* Bbase = B + (size_t)n0 * K2;

    float acc[4][4][4];
    #pragma unroll
    for (int i = 0; i < 4; i++)
        #pragma unroll
        for (int j = 0; j < 4; j++)
            #pragma unroll
            for (int r = 0; r < 4; r++) acc[i][j][r] = 0.f;

    const int nch = K2 / GBK;

    // ---- stage loader ----
    auto load_stage = [&](int c, int s) {
        uint32_t as = sb + s * STGB;
        uint32_t bs = as + OPB;
        const __nv_bfloat16* Ag = Abase + c * GBK;
        const __nv_bfloat16* Bg = Bbase + c * GBK;
        #pragma unroll
        for (int i = 0; i < 2; i++) {
            int row = ldrow + i * 64;
            cp16(as + row * AROWB + ldc16 * 16, Ag + (size_t)row * K2 + ldc16 * 8);
            cp16(bs + row * AROWB + ldc16 * 16, Bg + (size_t)row * K2 + ldc16 * 8);
        }
    };

    load_stage(0, 0);
    asm volatile("cp.async.commit_group;");
    if (nch > 1) load_stage(1, 1);
    asm volatile("cp.async.commit_group;");

    for (int c = 0; c < nch; c++) {
        asm volatile("cp.async.wait_group 1;");
        __syncthreads();

        // prefetch c+2
        if (c + 2 < nch) load_stage(c + 2, (c + 2) % GNST);
        asm volatile("cp.async.commit_group;");

        int s = c % GNST;
        uint32_t abase = sb + s * STGB;
        uint32_t bbase = abase + OPB;

        #pragma unroll
        for (int ks = 0; ks < 2; ks++) {
            uint32_t a[4][4];
            #pragma unroll
            for (int i = 0; i < 4; i++) {
                uint32_t addr = abase + (wm + i * 16 + (lane & 15)) * AROWB
                              + (ks * 2 + (lane >> 4)) * 16;
                asm volatile("ldmatrix.sync.aligned.m8n8.x4.shared.b16 {%0,%1,%2,%3}, [%4];"
                             : "=r"(a[i][0]), "=r"(a[i][1]), "=r"(a[i][2]), "=r"(a[i][3])
                             : "r"(addr));
            }
            uint32_t b[4][2];
            #pragma unroll
            for (int j = 0; j < 4; j++) {
                int l = lane & 15;
                uint32_t addr = bbase + (wn + j * 8 + (l & 7)) * AROWB
                              + (ks * 2 + ((l >> 3) & 1)) * 16;
                asm volatile("ldmatrix.sync.aligned.m8n8.x2.shared.b16 {%0,%1}, [%2];"
                             : "=r"(b[j][0]), "=r"(b[j][1]) : "r"(addr));
            }
            #pragma unroll
            for (int i = 0; i < 4; i++)
                #pragma unroll
                for (int j = 0; j < 4; j++) {
                    asm volatile(
                        "mma.sync.aligned.m16n8k16.row.col.f32.bf16.bf16.f32 "
                        "{%0,%1,%2,%3}, {%4,%5,%6,%7}, {%8,%9}, {%0,%1,%2,%3};"
                        : "+f"(acc[i][j][0]), "+f"(acc[i][j][1]),
                          "+f"(acc[i][j][2]), "+f"(acc[i][j][3])
                        : "r"(a[i][0]), "r"(a[i][1]), "r"(a[i][2]), "r"(a[i][3]),
                          "r"(b[j][0]), "r"(b[j][1]));
                }
        }
        __syncthreads();
    }

    // ---- epilogue: direct global writes ----
    #pragma unroll
    for (int i = 0; i < 4; i++) {
        int row = m0 + wm + i * 16 + (lane >> 2);
        #pragma unroll
        for (int j = 0; j < 4; j++) {
            int col = n0 + wn + j * 8 + (lane & 3) * 2;
            size_t o0 = (size_t)row * N + col;
            size_t o1 = (size_t)(row + 8) * N + col;
            float2 v0 = make_float2(acc[i][j][0], acc[i][j][1]);
            float2 v1 = make_float2(acc[i][j][2], acc[i][j][3]);
            if (RES) {
                float2 r0 = *(const float2*)(R + o0);
                float2 r1 = *(const float2*)(R + o1);
                v0.x += r0.x; v0.y += r0.y;
                v1.x += r1.x; v1.y += r1.y;
            }
            *(float2*)(C + o0) = v0;
            *(float2*)(C + o1) = v1;
        }
    }
}

// ---------------- RoPE on q and k in-place ----------------
__global__ void rope_k(float* __restrict__ q, float* __restrict__ k,
                       const float* __restrict__ fc, const float* __restrict__ fs) {
    int i = blockIdx.x * blockDim.x + threadIdx.x;
    if (i >= SQ * NH * (HD / 2)) return;
    int p = i & 63;
    int h = (i >> 6) & (NH - 1);
    int s = i >> 10;
    float c = fc[s * 64 + p], sn = fs[s * 64 + p];
    size_t base = (size_t)s * DIM + h * HD + 2 * p;
    float2 qv = *(float2*)(q + base);
    float2 kv = *(float2*)(k + base);
    *(float2*)(q + base) = make_float2(qv.x * c - qv.y * sn, qv.x * sn + qv.y * c);
    *(float2*)(k + base) = make_float2(kv.x * c - kv.y * sn, kv.x * sn + kv.y * c);
}

// ---------------- causal flash attention (fp32) -> split-bf16 output ----------------
#define BQ 32
#define BKK 32
#define KPAD 132
#define SCPAD 33
#define ATTN_SMEM ((BQ * KPAD + 2 * BKK * KPAD + BQ * SCPAD) * 4)

__global__ __launch_bounds__(256) void attn_k(
    const float* __restrict__ q, const float* __restrict__ k,
    const float* __restrict__ v, __nv_bfloat16* __restrict__ ob) {
    extern __shared__ float smf[];
    float* Qs = smf;
    float* Ks = Qs + BQ * KPAD;
    float* Vs = Ks + BKK * KPAD;
    float* sc = Vs + BKK * KPAD;

    int tid = threadIdx.x;
    int h = blockIdx.y;
    int q0 = blockIdx.x * BQ;

    #pragma unroll
    for (int r = 0; r < 4; r++) {
        int idx = tid + 256 * r;
        int row = idx >> 5;
        int c4 = (idx & 31) << 2;
        *(float4*)(&Qs[row * KPAD + c4]) =
            *(const float4*)(q + (size_t)(q0 + row) * DIM + h * HD + c4);
    }

    int qr = tid >> 3;
    int kl = tid & 7;
    int qg = q0 + qr;

    float m = -INFINITY, l = 0.f;
    float4 acc4[4];
    #pragma unroll
    for (int ii = 0; ii < 4; ii++) acc4[ii] = make_float4(0.f, 0.f, 0.f, 0.f);

    const float scale = 0.08838834764831845f;
    int ntiles = blockIdx.x + 1;

    for (int t = 0; t < ntiles; t++) {
        int j0 = t * BKK;
        __syncthreads();
        #pragma unroll
        for (int r = 0; r < 4; r++) {
            int idx = tid + 256 * r;
            int row = idx >> 5;
            int c4 = (idx & 31) << 2;
            *(float4*)(&Ks[row * KPAD + c4]) =
                *(const float4*)(k + (size_t)(j0 + row) * DIM + h * HD + c4);
            *(float4*)(&Vs[row * KPAD + c4]) =
                *(const float4*)(v + (size_t)(j0 + row) * DIM + h * HD + c4);
        }
        __syncthreads();

        float s0 = 0.f, s1 = 0.f, s2 = 0.f, s3 = 0.f;
        #pragma unroll 8
        for (int d = 0; d < HD; d += 4) {
            float4 q4 = *(const float4*)(&Qs[qr * KPAD + d]);
            float4 k0v = *(const float4*)(&Ks[(kl + 0)  * KPAD + d]);
            float4 k1v = *(const float4*)(&Ks[(kl + 8)  * KPAD + d]);
            float4 k2v = *(const float4*)(&Ks[(kl + 16) * KPAD + d]);
            float4 k3v = *(const float4*)(&Ks[(kl + 24) * KPAD + d]);
            s0 += q4.x * k0v.x + q4.y * k0v.y + q4.z * k0v.z + q4.w * k0v.w;
            s1 += q4.x * k1v.x + q4.y * k1v.y + q4.z * k1v.z + q4.w * k1v.w;
            s2 += q4.x * k2v.x + q4.y * k2v.y + q4.z * k2v.z + q4.w * k2v.w;
            s3 += q4.x * k3v.x + q4.y * k3v.y + q4.z * k3v.z + q4.w * k3v.w;
        }
        float sv[4] = {s0, s1, s2, s3};
        #pragma unroll
        for (int i = 0; i < 4; i++) {
            int j = kl + 8 * i;
            float s = sv[i] * scale;
            if (j0 + j > qg) s = -INFINITY;
            sc[qr * SCPAD + j] = s;
        }
        __syncthreads();

        float tmax = -INFINITY;
        #pragma unroll 8
        for (int j = 0; j < BKK; j++) tmax = fmaxf(tmax, sc[qr * SCPAD + j]);
        float nm = fmaxf(m, tmax);
        float alpha = __expf(m - nm);
        __syncthreads();

        #pragma unroll
        for (int i = 0; i < 4; i++) {
            int j = kl + 8 * i;
            float s = sc[qr * SCPAD + j];
            sc[qr * SCPAD + j] = (s == -INFINITY) ? 0.f : __expf(s - nm);
        }
        __syncthreads();

        float ps = 0.f;
        #pragma unroll 8
        for (int j = 0; j < BKK; j++) ps += sc[qr * SCPAD + j];
        l = l * alpha + ps;
        m = nm;

        #pragma unroll
        for (int ii = 0; ii < 4; ii++) {
            acc4[ii].x *= alpha; acc4[ii].y *= alpha;
            acc4[ii].z *= alpha; acc4[ii].w *= alpha;
        }
        #pragma unroll 4
        for (int j = 0; j < BKK; j++) {
            float p = sc[qr * SCPAD + j];
            #pragma unroll
            for (int ii = 0; ii < 4; ii++) {
                float4 vv = *(const float4*)(&Vs[j * KPAD + kl * 4 + 32 * ii]);
                acc4[ii].x += p * vv.x; acc4[ii].y += p * vv.y;
                acc4[ii].z += p * vv.z; acc4[ii].w += p * vv.w;
            }
        }
    }

    float invl = 1.f / l;
    __nv_bfloat16* op = ob + (size_t)3 * ((size_t)qg * DIM + h * HD);
    #pragma unroll
    for (int ii = 0; ii < 4; ii++) {
        float vals[4] = {acc4[ii].x * invl, acc4[ii].y * invl, acc4[ii].z * invl, acc4[ii].w * invl};
        #pragma unroll
        for (int c = 0; c < 4; c++) {
            int d = kl * 4 + 32 * ii + c;
            split3_A(vals[c], op + 3 * d);
        }
    }
}

// ---------------- launcher ----------------
extern "C" void kernel_launch(void* const* d_in, const int* in_sizes, int n_in,
                              void* d_out, int out_size) {
    const float* x  = (const float*)d_in[0];
    const float* fc = (const float*)d_in[1];
    const float* fs = (const float*)d_in[2];
    const float* wq = (const float*)d_in[4];
    const float* wk = (const float*)d_in[5];
    const float* wv = (const float*)d_in[6];
    const float* wo = (const float*)d_in[7];
    const float* w1 = (const float*)d_in[8];
    const float* w2 = (const float*)d_in[9];
    const float* w3 = (const float*)d_in[10];
    const float* ga = (const float*)d_in[11];
    const float* gf = (const float*)d_in[12];
    float* out = (float*)d_out;

    float *q, *k, *v, *h, *f1, *f3;
    __nv_bfloat16 *xnb, *aob, *hnb, *fgb, *wqt, *wkt, *wvt, *wot, *w1t, *w3t, *w2t;
    cudaGetSymbolAddress((void**)&q,   g_q);
    cudaGetSymbolAddress((void**)&k,   g_k);
    cudaGetSymbolAddress((void**)&v,   g_v);
    cudaGetSymbolAddress((void**)&h,   g_h);
    cudaGetSymbolAddress((void**)&f1,  g_f1);
    cudaGetSymbolAddress((void**)&f3,  g_f3);
    cudaGetSymbolAddress((void**)&xnb, g_xnb);
    cudaGetSymbolAddress((void**)&aob, g_aob);
    cudaGetSymbolAddress((void**)&hnb, g_hnb);
    cudaGetSymbolAddress((void**)&fgb, g_fgb);
    cudaGetSymbolAddress((void**)&wqt, g_wqt);
    cudaGetSymbolAddress((void**)&wkt, g_wkt);
    cudaGetSymbolAddress((void**)&wvt, g_wvt);
    cudaGetSymbolAddress((void**)&wot, g_wot);
    cudaGetSymbolAddress((void**)&w1t, g_w1t);
    cudaGetSymbolAddress((void**)&w3t, g_w3t);
    cudaGetSymbolAddress((void**)&w2t, g_w2t);

    cudaFuncSetAttribute(attn_k, cudaFuncAttributeMaxDynamicSharedMemorySize, ATTN_SMEM);
    cudaFuncSetAttribute(hgemm_k<0>, cudaFuncAttributeMaxDynamicSharedMemorySize, HGEMM_SMEM);
    cudaFuncSetAttribute(hgemm_k<1>, cudaFuncAttributeMaxDynamicSharedMemorySize, HGEMM_SMEM);

    // weight conversions (transpose + 3-way split)
    convert_w_t<<<dim3(DIM / 32, DIM / 32), 256>>>(wq, wqt, DIM, DIM);
    convert_w_t<<<dim3(DIM / 32, DIM / 32), 256>>>(wk, wkt, DIM, DIM);
    convert_w_t<<<dim3(DIM / 32, DIM / 32), 256>>>(wv, wvt, DIM, DIM);
    convert_w_t<<<dim3(DIM / 32, DIM / 32), 256>>>(wo, wot, DIM, DIM);
    convert_w_t<<<dim3(DIM / 32, HID / 32), 256>>>(w1, w1t, DIM, HID);
    convert_w_t<<<dim3(DIM / 32, HID / 32), 256>>>(w3, w3t, DIM, HID);
    convert_w_t<<<dim3(HID / 32, DIM / 32), 256>>>(w2, w2t, HID, DIM);

    // 1. pre-attn rmsnorm -> split
    rmsnorm_big_k<<<SQ, 256>>>(x, ga, xnb);

    // 2. q,k,v projections (HMMA)
    dim3 gDD(DIM / 128, SQ / 128);
    hgemm_k<0><<<gDD, 256, HGEMM_SMEM>>>(xnb, wqt, nullptr, q, SQ, DIM, K2_DIM);
    hgemm_k<0><<<gDD, 256, HGEMM_SMEM>>>(xnb, wkt, nullptr, k, SQ, DIM, K2_DIM);
    hgemm_k<0><<<gDD, 256, HGEMM_SMEM>>>(xnb, wvt, nullptr, v, SQ, DIM, K2_DIM);

    // 3. rope
    rope_k<<<(SQ * NH * (HD / 2)) / 256, 256>>>(q, k, fc, fs);

    // 4. attention -> split-bf16
    attn_k<<<dim3(SQ / BQ, NH), 256, ATTN_SMEM>>>(q, k, v, aob);

    // 5. output projection + residual
    hgemm_k<1><<<gDD, 256, HGEMM_SMEM>>>(aob, wot, x, h, SQ, DIM, K2_DIM);

    // 6. pre-ffn rmsnorm -> split
    rmsnorm_big_k<<<SQ, 256>>>(h, gf, hnb);

    // 7. ffn up projections
    dim3 gDH(HID / 128, SQ / 128);
    hgemm_k<0><<<gDH, 256, HGEMM_SMEM>>>(hnb, w1t, nullptr, f1, SQ, HID, K2_DIM);
    hgemm_k<0><<<gDH, 256, HGEMM_SMEM>>>(hnb, w3t, nullptr, f3, SQ, HID, K2_DIM);

    // 8. silu gate -> split
    silu_big_k<<<(SQ * HID + 255) / 256, 256>>>(f1, f3, fgb, SQ * HID);

    // 9. down projection + residual -> output
    hgemm_k<1><<<gDD, 256, HGEMM_SMEM>>>(fgb, w2t, h, out, SQ, DIM, K2_HID);
}

// round 5
// speedup vs baseline: 1.8875x; 1.1049x over previous
#include <cuda_runtime.h>
#include <cuda_bf16.h>
#include <math.h>
#include <stdint.h>

#define SQ 2048
#define DIM 2048
#define NH 16
#define HD 128
#define HID 5632

// K-expanded split-bf16: K2 = 3*K
#define K2_DIM (3 * DIM)   // 6144
#define K2_HID (3 * HID)   // 16896

__device__ __forceinline__ uint32_t smem_u32(const void* p) {
    uint32_t a;
    asm("{ .reg .u64 t; cvta.to.shared.u64 t, %1; cvt.u32.u64 %0, t; }" : "=r"(a) : "l"(p));
    return a;
}
__device__ __forceinline__ void cp16(uint32_t s, const void* g) {
    asm volatile("cp.async.cg.shared.global [%0], [%1], 16;" :: "r"(s), "l"(g));
}

// ---------------- scratch ----------------
__device__ float g_q [SQ * DIM];
__device__ float g_k [SQ * DIM];
__device__ float g_v [SQ * DIM];
__device__ float g_h [SQ * DIM];
__device__ float g_f1[SQ * HID];
__device__ float g_f3[SQ * HID];

__device__ __nv_bfloat16 g_xnb[SQ * K2_DIM];
__device__ __nv_bfloat16 g_aob[SQ * K2_DIM];
__device__ __nv_bfloat16 g_hnb[SQ * K2_DIM];
__device__ __nv_bfloat16 g_fgb[SQ * K2_HID];
__device__ __nv_bfloat16 g_wqkvt[3 * DIM * K2_DIM];   // rows: [wq | wk | wv]
__device__ __nv_bfloat16 g_wot  [DIM * K2_DIM];
__device__ __nv_bfloat16 g_w13t [2 * HID * K2_DIM];   // rows: [w1 | w3]
__device__ __nv_bfloat16 g_w2t  [DIM * K2_HID];

__device__ __forceinline__ void split3_A(float x, __nv_bfloat16* p) {
    __nv_bfloat16 hi = __float2bfloat16(x);
    __nv_bfloat16 lo = __float2bfloat16(x - __bfloat162float(hi));
    p[0] = hi; p[1] = lo; p[2] = hi;   // A side: {hi, lo, hi}
}
__device__ __forceinline__ void split3_B(float x, __nv_bfloat16* p) {
    __nv_bfloat16 hi = __float2bfloat16(x);
    __nv_bfloat16 lo = __float2bfloat16(x - __bfloat162float(hi));
    p[0] = hi; p[1] = hi; p[2] = lo;   // B side: {hi, hi, lo}
}

// ---------------- weight transpose + split: W[K,N] -> Wt[N, 3K] ----------------
__global__ void convert_w_t(const float* __restrict__ W, __nv_bfloat16* __restrict__ Wt,
                            int K, int N) {
    __shared__ float s[32][33];
    int k0 = blockIdx.x * 32, n0 = blockIdx.y * 32;
    int tx = threadIdx.x & 31, ty = threadIdx.x >> 5;  // 256 threads
    #pragma unroll
    for (int r = 0; r < 4; r++) {
        int k = ty + r * 8;
        s[k][tx] = W[(size_t)(k0 + k) * N + n0 + tx];
    }
    __syncthreads();
    int K3 = 3 * K;
    #pragma unroll
    for (int r = 0; r < 4; r++) {
        int n = ty + r * 8;
        split3_B(s[tx][n], Wt + (size_t)(n0 + n) * K3 + 3 * (k0 + tx));
    }
}

// ---------------- rmsnorm -> split-bf16 A operand ----------------
__global__ void rmsnorm_big_k(const float* __restrict__ x, const float* __restrict__ g,
                              __nv_bfloat16* __restrict__ o) {
    int row = blockIdx.x;
    const float* xr = x + (size_t)row * DIM;
    float ss = 0.f;
    for (int i = threadIdx.x; i < DIM; i += blockDim.x) { float v = xr[i]; ss += v * v; }
    __shared__ float red[32];
    int lane = threadIdx.x & 31, w = threadIdx.x >> 5;
    #pragma unroll
    for (int off = 16; off; off >>= 1) ss += __shfl_xor_sync(0xffffffffu, ss, off);
    if (lane == 0) red[w] = ss;
    __syncthreads();
    if (w == 0) {
        float v = (lane < (int)(blockDim.x >> 5)) ? red[lane] : 0.f;
        #pragma unroll
        for (int off = 16; off; off >>= 1) v += __shfl_xor_sync(0xffffffffu, v, off);
        if (lane == 0) red[0] = v;
    }
    __syncthreads();
    float inv = rsqrtf(red[0] / (float)DIM + 1e-6f);
    __nv_bfloat16* orow = o + (size_t)row * (3 * DIM);
    for (int i = threadIdx.x; i < DIM; i += blockDim.x)
        split3_A(g[i] * xr[i] * inv, orow + 3 * i);
}

// ---------------- silu(f1)*f3 -> split-bf16 A operand ----------------
__global__ void silu_big_k(const float* __restrict__ a, const float* __restrict__ b,
                           __nv_bfloat16* __restrict__ o, int n) {
    int i = blockIdx.x * blockDim.x + threadIdx.x;
    if (i >= n) return;
    float av = a[i];
    float v = av / (1.f + __expf(-av)) * b[i];
    split3_A(v, o + (size_t)3 * i);
}

// ---------------- HMMA bf16 GEMM ----------------
// C[M,Ntot] = A[M,K2] @ B[Ntot,K2]^T (+R), output scattered to up to 3 targets
// of Nout columns each (nblk_per 128-col blocks per target).
// CTA 128x128, 8 warps (2x4), warp 64x32, BK=64, 3-stage cp.async, 1 barrier/chunk.
#define GBM 128
#define GBN 128
#define GBK 64
#define AROWB 144                 // 128B data + 16B pad per smem row
#define OPB (128 * AROWB)         // 18432 bytes per operand per stage
#define STGB (2 * OPB)            // 36864 per stage
#define GNST 3
#define HGEMM_SMEM (GNST * STGB)  // 110592

template <int RES>
__global__ __launch_bounds__(256, 2) void hgemm_k(
    const __nv_bfloat16* __restrict__ A, const __nv_bfloat16* __restrict__ B,
    const float* __restrict__ R,
    float* __restrict__ C0, float* __restrict__ C1, float* __restrict__ C2,
    int nblk_per, int M, int Nout, int K2) {
    extern __shared__ char sm[];
    uint32_t sb = smem_u32(sm);

    const int tid = threadIdx.x;
    const int wid = tid >> 5, lane = tid & 31;
    const int m0 = blockIdx.y * GBM;
    const int wm = (wid >> 2) * 64;
    const int wn = (wid & 3) * 32;

    // loader coords: 128 rows x 8 chunks of 16B, 1024 cp16 per operand, 4/thread
    const __nv_bfloat16* Abase = A + (size_t)m0 * K2;
    const __nv_bfloat16* Bbase = B + (size_t)blockIdx.x * GBN * K2;

    float acc[4][4][4];
    #pragma unroll
    for (int i = 0; i < 4; i++)
        #pragma unroll
        for (int j = 0; j < 4; j++)
            #pragma unroll
            for (int r = 0; r < 4; r++) acc[i][j][r] = 0.f;

    const int nch = K2 / GBK;

    auto load_stage = [&](int c, int s) {
        uint32_t as = sb + s * STGB;
        uint32_t bs = as + OPB;
        const __nv_bfloat16* Ag = Abase + c * GBK;
        const __nv_bfloat16* Bg = Bbase + c * GBK;
        #pragma unroll
        for (int i = 0; i < 4; i++) {
            int idx = tid + 256 * i;
            int row = idx >> 3, ch = idx & 7;
            cp16(as + row * AROWB + ch * 16, Ag + (size_t)row * K2 + ch * 8);
            cp16(bs + row * AROWB + ch * 16, Bg + (size_t)row * K2 + ch * 8);
        }
    };

    load_stage(0, 0);
    asm volatile("cp.async.commit_group;");
    if (nch > 1) load_stage(1, 1);
    asm volatile("cp.async.commit_group;");

    for (int c = 0; c < nch; c++) {
        asm volatile("cp.async.wait_group 1;");
        __syncthreads();

        if (c + 2 < nch) load_stage(c + 2, (c + 2) % GNST);
        asm volatile("cp.async.commit_group;");

        int s = c % GNST;
        uint32_t abase = sb + s * STGB;
        uint32_t bbase = abase + OPB;

        #pragma unroll
        for (int ks = 0; ks < 4; ks++) {
            uint32_t a[4][4];
            #pragma unroll
            for (int i = 0; i < 4; i++) {
                uint32_t addr = abase + (wm + i * 16 + (lane & 15)) * AROWB
                              + (ks * 2 + (lane >> 4)) * 16;
                asm volatile("ldmatrix.sync.aligned.m8n8.x4.shared.b16 {%0,%1,%2,%3}, [%4];"
                             : "=r"(a[i][0]), "=r"(a[i][1]), "=r"(a[i][2]), "=r"(a[i][3])
                             : "r"(addr));
            }
            uint32_t b[4][2];
            #pragma unroll
            for (int j = 0; j < 4; j++) {
                int l = lane & 15;
                uint32_t addr = bbase + (wn + j * 8 + (l & 7)) * AROWB
                              + (ks * 2 + ((l >> 3) & 1)) * 16;
                asm volatile("ldmatrix.sync.aligned.m8n8.x2.shared.b16 {%0,%1}, [%2];"
                             : "=r"(b[j][0]), "=r"(b[j][1]) : "r"(addr));
            }
            #pragma unroll
            for (int i = 0; i < 4; i++)
                #pragma unroll
                for (int j = 0; j < 4; j++) {
                    asm volatile(
                        "mma.sync.aligned.m16n8k16.row.col.f32.bf16.bf16.f32 "
                        "{%0,%1,%2,%3}, {%4,%5,%6,%7}, {%8,%9}, {%0,%1,%2,%3};"
                        : "+f"(acc[i][j][0]), "+f"(acc[i][j][1]),
                          "+f"(acc[i][j][2]), "+f"(acc[i][j][3])
                        : "r"(a[i][0]), "r"(a[i][1]), "r"(a[i][2]), "r"(a[i][3]),
                          "r"(b[j][0]), "r"(b[j][1]));
                }
        }
    }

    // ---- epilogue: scatter to target buffer ----
    int t = blockIdx.x / nblk_per;
    float* C = (t == 0) ? C0 : ((t == 1) ? C1 : C2);
    int n0 = (blockIdx.x % nblk_per) * GBN;

    #pragma unroll
    for (int i = 0; i < 4; i++) {
        int row = m0 + wm + i * 16 + (lane >> 2);
        #pragma unroll
        for (int j = 0; j < 4; j++) {
            int col = n0 + wn + j * 8 + (lane & 3) * 2;
            size_t o0 = (size_t)row * Nout + col;
            size_t o1 = (size_t)(row + 8) * Nout + col;
            float2 v0 = make_float2(acc[i][j][0], acc[i][j][1]);
            float2 v1 = make_float2(acc[i][j][2], acc[i][j][3]);
            if (RES) {
                float2 r0 = *(const float2*)(R + o0);
                float2 r1 = *(const float2*)(R + o1);
                v0.x += r0.x; v0.y += r0.y;
                v1.x += r1.x; v1.y += r1.y;
            }
            *(float2*)(C + o0) = v0;
            *(float2*)(C + o1) = v1;
        }
    }
}

// ---------------- RoPE on q and k in-place ----------------
__global__ void rope_k(float* __restrict__ q, float* __restrict__ k,
                       const float* __restrict__ fc, const float* __restrict__ fs) {
    int i = blockIdx.x * blockDim.x + threadIdx.x;
    if (i >= SQ * NH * (HD / 2)) return;
    int p = i & 63;
    int h = (i >> 6) & (NH - 1);
    int s = i >> 10;
    float c = fc[s * 64 + p], sn = fs[s * 64 + p];
    size_t base = (size_t)s * DIM + h * HD + 2 * p;
    float2 qv = *(float2*)(q + base);
    float2 kv = *(float2*)(k + base);
    *(float2*)(q + base) = make_float2(qv.x * c - qv.y * sn, qv.x * sn + qv.y * c);
    *(float2*)(k + base) = make_float2(kv.x * c - kv.y * sn, kv.x * sn + kv.y * c);
}

// ---------------- causal flash attention (fp32) -> split-bf16 output ----------------
#define BQ 32
#define BKK 32
#define KPAD 132
#define SCPAD 33
#define ATTN_SMEM ((BQ * KPAD + 2 * BKK * KPAD + BQ * SCPAD) * 4)

__global__ __launch_bounds__(256) void attn_k(
    const float* __restrict__ q, const float* __restrict__ k,
    const float* __restrict__ v, __nv_bfloat16* __restrict__ ob) {
    extern __shared__ float smf[];
    float* Qs = smf;
    float* Ks = Qs + BQ * KPAD;
    float* Vs = Ks + BKK * KPAD;
    float* sc = Vs + BKK * KPAD;

    int tid = threadIdx.x;
    int h = blockIdx.y;
    int q0 = blockIdx.x * BQ;

    #pragma unroll
    for (int r = 0; r < 4; r++) {
        int idx = tid + 256 * r;
        int row = idx >> 5;
        int c4 = (idx & 31) << 2;
        *(float4*)(&Qs[row * KPAD + c4]) =
            *(const float4*)(q + (size_t)(q0 + row) * DIM + h * HD + c4);
    }

    int qr = tid >> 3;
    int kl = tid & 7;
    int qg = q0 + qr;

    float m = -INFINITY, l = 0.f;
    float4 acc4[4];
    #pragma unroll
    for (int ii = 0; ii < 4; ii++) acc4[ii] = make_float4(0.f, 0.f, 0.f, 0.f);

    const float scale = 0.08838834764831845f;
    int ntiles = blockIdx.x + 1;

    for (int t = 0; t < ntiles; t++) {
        int j0 = t * BKK;
        __syncthreads();
        #pragma unroll
        for (int r = 0; r < 4; r++) {
            int idx = tid + 256 * r;
            int row = idx >> 5;
            int c4 = (idx & 31) << 2;
            *(float4*)(&Ks[row * KPAD + c4]) =
                *(const float4*)(k + (size_t)(j0 + row) * DIM + h * HD + c4);
            *(float4*)(&Vs[row * KPAD + c4]) =
                *(const float4*)(v + (size_t)(j0 + row) * DIM + h * HD + c4);
        }
        __syncthreads();

        float s0 = 0.f, s1 = 0.f, s2 = 0.f, s3 = 0.f;
        #pragma unroll 8
        for (int d = 0; d < HD; d += 4) {
            float4 q4 = *(const float4*)(&Qs[qr * KPAD + d]);
            float4 k0v = *(const float4*)(&Ks[(kl + 0)  * KPAD + d]);
            float4 k1v = *(const float4*)(&Ks[(kl + 8)  * KPAD + d]);
            float4 k2v = *(const float4*)(&Ks[(kl + 16) * KPAD + d]);
            float4 k3v = *(const float4*)(&Ks[(kl + 24) * KPAD + d]);
            s0 += q4.x * k0v.x + q4.y * k0v.y + q4.z * k0v.z + q4.w * k0v.w;
            s1 += q4.x * k1v.x + q4.y * k1v.y + q4.z * k1v.z + q4.w * k1v.w;
            s2 += q4.x * k2v.x + q4.y * k2v.y + q4.z * k2v.z + q4.w * k2v.w;
            s3 += q4.x * k3v.x + q4.y * k3v.y + q4.z * k3v.z + q4.w * k3v.w;
        }
        float sv[4] = {s0, s1, s2, s3};
        #pragma unroll
        for (int i = 0; i < 4; i++) {
            int j = kl + 8 * i;
            float s = sv[i] * scale;
            if (j0 + j > qg) s = -INFINITY;
            sc[qr * SCPAD + j] = s;
        }
        __syncthreads();

        float tmax = -INFINITY;
        #pragma unroll 8
        for (int j = 0; j < BKK; j++) tmax = fmaxf(tmax, sc[qr * SCPAD + j]);
        float nm = fmaxf(m, tmax);
        float alpha = __expf(m - nm);
        __syncthreads();

        #pragma unroll
        for (int i = 0; i < 4; i++) {
            int j = kl + 8 * i;
            float s = sc[qr * SCPAD + j];
            sc[qr * SCPAD + j] = (s == -INFINITY) ? 0.f : __expf(s - nm);
        }
        __syncthreads();

        float ps = 0.f;
        #pragma unroll 8
        for (int j = 0; j < BKK; j++) ps += sc[qr * SCPAD + j];
        l = l * alpha + ps;
        m = nm;

        #pragma unroll
        for (int ii = 0; ii < 4; ii++) {
            acc4[ii].x *= alpha; acc4[ii].y *= alpha;
            acc4[ii].z *= alpha; acc4[ii].w *= alpha;
        }
        #pragma unroll 4
        for (int j = 0; j < BKK; j++) {
            float p = sc[qr * SCPAD + j];
            #pragma unroll
            for (int ii = 0; ii < 4; ii++) {
                float4 vv = *(const float4*)(&Vs[j * KPAD + kl * 4 + 32 * ii]);
                acc4[ii].x += p * vv.x; acc4[ii].y += p * vv.y;
                acc4[ii].z += p * vv.z; acc4[ii].w += p * vv.w;
            }
        }
    }

    float invl = 1.f / l;
    __nv_bfloat16* op = ob + (size_t)3 * ((size_t)qg * DIM + h * HD);
    #pragma unroll
    for (int ii = 0; ii < 4; ii++) {
        float vals[4] = {acc4[ii].x * invl, acc4[ii].y * invl, acc4[ii].z * invl, acc4[ii].w * invl};
        #pragma unroll
        for (int c = 0; c < 4; c++) {
            int d = kl * 4 + 32 * ii + c;
            split3_A(vals[c], op + 3 * d);
        }
    }
}

// ---------------- launcher ----------------
extern "C" void kernel_launch(void* const* d_in, const int* in_sizes, int n_in,
                              void* d_out, int out_size) {
    const float* x  = (const float*)d_in[0];
    const float* fc = (const float*)d_in[1];
    const float* fs = (const float*)d_in[2];
    const float* wq = (const float*)d_in[4];
    const float* wk = (const float*)d_in[5];
    const float* wv = (const float*)d_in[6];
    const float* wo = (const float*)d_in[7];
    const float* w1 = (const float*)d_in[8];
    const float* w2 = (const float*)d_in[9];
    const float* w3 = (const float*)d_in[10];
    const float* ga = (const float*)d_in[11];
    const float* gf = (const float*)d_in[12];
    float* out = (float*)d_out;

    float *q, *k, *v, *h, *f1, *f3;
    __nv_bfloat16 *xnb, *aob, *hnb, *fgb, *wqkvt, *wot, *w13t, *w2t;
    cudaGetSymbolAddress((void**)&q,   g_q);
    cudaGetSymbolAddress((void**)&k,   g_k);
    cudaGetSymbolAddress((void**)&v,   g_v);
    cudaGetSymbolAddress((void**)&h,   g_h);
    cudaGetSymbolAddress((void**)&f1,  g_f1);
    cudaGetSymbolAddress((void**)&f3,  g_f3);
    cudaGetSymbolAddress((void**)&xnb, g_xnb);
    cudaGetSymbolAddress((void**)&aob, g_aob);
    cudaGetSymbolAddress((void**)&hnb, g_hnb);
    cudaGetSymbolAddress((void**)&fgb, g_fgb);
    cudaGetSymbolAddress((void**)&wqkvt, g_wqkvt);
    cudaGetSymbolAddress((void**)&wot,   g_wot);
    cudaGetSymbolAddress((void**)&w13t,  g_w13t);
    cudaGetSymbolAddress((void**)&w2t,   g_w2t);

    cudaFuncSetAttribute(attn_k, cudaFuncAttributeMaxDynamicSharedMemorySize, ATTN_SMEM);
    cudaFuncSetAttribute(hgemm_k<0>, cudaFuncAttributeMaxDynamicSharedMemorySize, HGEMM_SMEM);
    cudaFuncSetAttribute(hgemm_k<1>, cudaFuncAttributeMaxDynamicSharedMemorySize, HGEMM_SMEM);

    // weight conversions (transpose + 3-way split) into concatenated B layouts
    convert_w_t<<<dim3(DIM / 32, DIM / 32), 256>>>(wq, wqkvt, DIM, DIM);
    convert_w_t<<<dim3(DIM / 32, DIM / 32), 256>>>(wk, wqkvt + (size_t)DIM * K2_DIM, DIM, DIM);
    convert_w_t<<<dim3(DIM / 32, DIM / 32), 256>>>(wv, wqkvt + (size_t)2 * DIM * K2_DIM, DIM, DIM);
    convert_w_t<<<dim3(DIM / 32, DIM / 32), 256>>>(wo, wot, DIM, DIM);
    convert_w_t<<<dim3(DIM / 32, HID / 32), 256>>>(w1, w13t, DIM, HID);
    convert_w_t<<<dim3(DIM / 32, HID / 32), 256>>>(w3, w13t + (size_t)HID * K2_DIM, DIM, HID);
    convert_w_t<<<dim3(HID / 32, DIM / 32), 256>>>(w2, w2t, HID, DIM);

    // 1. pre-attn rmsnorm -> split
    rmsnorm_big_k<<<SQ, 256>>>(x, ga, xnb);

    // 2. fused qkv projection
    hgemm_k<0><<<dim3(3 * DIM / 128, SQ / 128), 256, HGEMM_SMEM>>>(
        xnb, wqkvt, nullptr, q, k, v, DIM / 128, SQ, DIM, K2_DIM);

    // 3. rope
    rope_k<<<(SQ * NH * (HD / 2)) / 256, 256>>>(q, k, fc, fs);

    // 4. attention -> split-bf16
    attn_k<<<dim3(SQ / BQ, NH), 256, ATTN_SMEM>>>(q, k, v, aob);

    // 5. output projection + residual
    hgemm_k<1><<<dim3(DIM / 128, SQ / 128), 256, HGEMM_SMEM>>>(
        aob, wot, x, h, h, h, DIM / 128, SQ, DIM, K2_DIM);

    // 6. pre-ffn rmsnorm -> split
    rmsnorm_big_k<<<SQ, 256>>>(h, gf, hnb);

    // 7. fused ffn up projections
    hgemm_k<0><<<dim3(2 * HID / 128, SQ / 128), 256, HGEMM_SMEM>>>(
        hnb, w13t, nullptr, f1, f3, f3, HID / 128, SQ, HID, K2_DIM);

    // 8. silu gate -> split
    silu_big_k<<<(SQ * HID + 255) / 256, 256>>>(f1, f3, fgb, SQ * HID);

    // 9. down projection + residual -> output
    hgemm_k<1><<<dim3(DIM / 128, SQ / 128), 256, HGEMM_SMEM>>>(
        fgb, w2t, h, out, out, out, DIM / 128, SQ, DIM, K2_HID);
}